// round 8
// baseline (speedup 1.0000x reference)
#include <cuda_runtime.h>
#include <cuda_bf16.h>
#include <math.h>

#define N_NODES 100864
#define N_EDGES 1613824
#define N_GRAPHS 512
#define IN_C 384
#define HID 128
#define OUT_C 2

// ---------------- scratch (static __device__, no allocs) ----------------
__device__ int   g_cnt[N_NODES];
__device__ int   g_rowptr[N_NODES + 1];
__device__ int   g_fill[N_NODES];
__device__ int   g_col[N_EDGES];
__device__ __align__(16) float g_dinv[N_NODES];
__device__ __align__(16) float g_bufA[(size_t)N_NODES * HID];
__device__ __align__(16) float g_bufB[(size_t)N_NODES * HID];
__device__ __align__(16) float g_pool[N_GRAPHS * HID];
__device__ __align__(16) float g_cntg[N_GRAPHS];

// ---------------- init: zero counters / pool ----------------
__global__ void init_kernel() {
    int i = blockIdx.x * blockDim.x + threadIdx.x;
    if (i < N_NODES) g_cnt[i] = 0;
    if (i < N_GRAPHS * HID) g_pool[i] = 0.0f;
    if (i < N_GRAPHS) g_cntg[i] = 0.0f;
}

// ---------------- degree count (dst side), 4 edges/thread ----------------
__global__ void count_kernel(const int* __restrict__ edge) {
    int e4 = blockIdx.x * blockDim.x + threadIdx.x;
    if (e4 >= N_EDGES / 4) return;
    int4 d = ((const int4*)(edge + N_EDGES))[e4];
    unsigned a = (unsigned)d.x, b = (unsigned)d.y, c = (unsigned)d.z, dd = (unsigned)d.w;
    if (a >= N_NODES) a = 0;
    if (b >= N_NODES) b = 0;
    if (c >= N_NODES) c = 0;
    if (dd >= N_NODES) dd = 0;
    atomicAdd(&g_cnt[a], 1);
    atomicAdd(&g_cnt[b], 1);
    atomicAdd(&g_cnt[c], 1);
    atomicAdd(&g_cnt[dd], 1);
}

// ---------------- single-block scan: rowptr, fill, dinv ----------------
__global__ void scan_kernel() {
    __shared__ int sh[1024];
    const int n = N_NODES;
    const int C = (n + 1023) / 1024;
    int t = threadIdx.x;
    int beg = t * C;
    int end = beg + C; if (end > n) end = n;
    int s = 0;
    for (int i = beg; i < end; i++) s += g_cnt[i];
    sh[t] = s;
    __syncthreads();
    for (int off = 1; off < 1024; off <<= 1) {
        int v = (t >= off) ? sh[t - off] : 0;
        __syncthreads();
        sh[t] += v;
        __syncthreads();
    }
    int run = (t == 0) ? 0 : sh[t - 1];
    for (int i = beg; i < end; i++) {
        int c = g_cnt[i];
        g_rowptr[i] = run;
        g_fill[i]   = run;
        g_dinv[i]   = rsqrtf((float)c + 1.0f);  // +1 self-loop
        run += c;
    }
    if (t == 1023) g_rowptr[n] = run;
}

// ---------------- CSR fill, 4 edges/thread ----------------
__global__ void fill_kernel(const int* __restrict__ edge) {
    int e4 = blockIdx.x * blockDim.x + threadIdx.x;
    if (e4 >= N_EDGES / 4) return;
    int4 s = ((const int4*)edge)[e4];
    int4 d = ((const int4*)(edge + N_EDGES))[e4];
    #pragma unroll
    for (int i = 0; i < 4; i++) {
        unsigned src = (unsigned)((i == 0) ? s.x : (i == 1) ? s.y : (i == 2) ? s.z : s.w);
        unsigned dst = (unsigned)((i == 0) ? d.x : (i == 1) ? d.y : (i == 2) ? d.z : d.w);
        if (src >= N_NODES) src = 0;
        if (dst >= N_NODES) dst = 0;
        int p = atomicAdd(&g_fill[dst], 1);
        g_col[p] = (int)src;
    }
}

// ---------------- tf32 helpers ----------------
__device__ __forceinline__ void split2(float x, unsigned& hi, unsigned& lo) {
    unsigned h; asm("cvt.rna.tf32.f32 %0, %1;" : "=r"(h) : "f"(x));
    float hf = __uint_as_float(h);
    unsigned l; asm("cvt.rna.tf32.f32 %0, %1;" : "=r"(l) : "f"(x - hf));
    hi = h; lo = l;
}
__device__ __forceinline__ void mma8(float* d, const unsigned* a, const unsigned* b) {
    asm("mma.sync.aligned.m16n8k8.row.col.f32.tf32.tf32.f32 "
        "{%0,%1,%2,%3},{%4,%5,%6,%7},{%8,%9},{%0,%1,%2,%3};"
        : "+f"(d[0]), "+f"(d[1]), "+f"(d[2]), "+f"(d[3])
        : "r"(a[0]), "r"(a[1]), "r"(a[2]), "r"(a[3]), "r"(b[0]), "r"(b[1]));
}

// ---- tensor-core GEMM: C[M,128] = A[M,K] @ B[K,128], 3xTF32, pre-split SMEM --
// block tile 128x128, BK=16, 8 warps (4 M x 2 N), warp tile 32x64 (2x8 m16n8k8)
template<int K>
__device__ __forceinline__ void mma_gemm_body(const float* __restrict__ A,
                                              const float* __restrict__ B,
                                              float* __restrict__ C) {
    __shared__ unsigned Ahi[16][136], Alo[16][136];   // pre-split tf32 bits
    __shared__ unsigned Bhi[16][136], Blo[16][136];   // 136: conflict-free tig step
    const int tid  = threadIdx.x;
    const int lane = tid & 31;
    const int warp = tid >> 5;
    const int g    = lane >> 2, tig = lane & 3;
    const int warpM = warp >> 1, warpN = warp & 1;
    const int rowBase = blockIdx.x * 128;

    float acc[2][8][4];
    #pragma unroll
    for (int mt = 0; mt < 2; mt++)
        #pragma unroll
        for (int nt = 0; nt < 8; nt++)
            #pragma unroll
            for (int i = 0; i < 4; i++) acc[mt][nt][i] = 0.0f;

    const int aRow = tid >> 1, aK = (tid & 1) * 8;   // A: 2 thr/row, 8 k each
    const int bK = tid >> 4,  bN = (tid & 15) * 8;   // B: 16 thr/row, 8 n each

    for (int k0 = 0; k0 < K; k0 += 16) {
        #pragma unroll
        for (int i = 0; i < 2; i++) {
            float4 v = *(const float4*)&A[(size_t)(rowBase + aRow) * K + (k0 + aK + i * 4)];
            split2(v.x, Ahi[aK + i * 4 + 0][aRow], Alo[aK + i * 4 + 0][aRow]);
            split2(v.y, Ahi[aK + i * 4 + 1][aRow], Alo[aK + i * 4 + 1][aRow]);
            split2(v.z, Ahi[aK + i * 4 + 2][aRow], Alo[aK + i * 4 + 2][aRow]);
            split2(v.w, Ahi[aK + i * 4 + 3][aRow], Alo[aK + i * 4 + 3][aRow]);
        }
        #pragma unroll
        for (int i = 0; i < 2; i++) {
            float4 v = *(const float4*)&B[(size_t)(k0 + bK) * 128 + bN + i * 4];
            split2(v.x, Bhi[bK][bN + i * 4 + 0], Blo[bK][bN + i * 4 + 0]);
            split2(v.y, Bhi[bK][bN + i * 4 + 1], Blo[bK][bN + i * 4 + 1]);
            split2(v.z, Bhi[bK][bN + i * 4 + 2], Blo[bK][bN + i * 4 + 2]);
            split2(v.w, Bhi[bK][bN + i * 4 + 3], Blo[bK][bN + i * 4 + 3]);
        }
        __syncthreads();
        #pragma unroll
        for (int kk = 0; kk < 2; kk++) {
            const int kb = kk * 8;
            unsigned ah[2][4], al[2][4];
            #pragma unroll
            for (int mt = 0; mt < 2; mt++) {
                int r0 = warpM * 32 + mt * 16 + g;
                ah[mt][0] = Ahi[kb + tig    ][r0];     al[mt][0] = Alo[kb + tig    ][r0];
                ah[mt][1] = Ahi[kb + tig    ][r0 + 8]; al[mt][1] = Alo[kb + tig    ][r0 + 8];
                ah[mt][2] = Ahi[kb + tig + 4][r0];     al[mt][2] = Alo[kb + tig + 4][r0];
                ah[mt][3] = Ahi[kb + tig + 4][r0 + 8]; al[mt][3] = Alo[kb + tig + 4][r0 + 8];
            }
            #pragma unroll
            for (int nt = 0; nt < 8; nt++) {
                int c0 = warpN * 64 + nt * 8 + g;
                unsigned bh[2], bl[2];
                bh[0] = Bhi[kb + tig    ][c0]; bl[0] = Blo[kb + tig    ][c0];
                bh[1] = Bhi[kb + tig + 4][c0]; bl[1] = Blo[kb + tig + 4][c0];
                #pragma unroll
                for (int mt = 0; mt < 2; mt++) {
                    mma8(acc[mt][nt], ah[mt], bh);   // hi*hi
                    mma8(acc[mt][nt], al[mt], bh);   // lo*hi
                    mma8(acc[mt][nt], ah[mt], bl);   // hi*lo
                }
            }
        }
        __syncthreads();
    }
    #pragma unroll
    for (int mt = 0; mt < 2; mt++) {
        #pragma unroll
        for (int nt = 0; nt < 8; nt++) {
            int r = rowBase + warpM * 32 + mt * 16 + g;
            int c = warpN * 64 + nt * 8 + tig * 2;
            *(float2*)&C[(size_t)r * 128 + c]       = make_float2(acc[mt][nt][0], acc[mt][nt][1]);
            *(float2*)&C[(size_t)(r + 8) * 128 + c] = make_float2(acc[mt][nt][2], acc[mt][nt][3]);
        }
    }
}

__global__ __launch_bounds__(256, 2)
void gemm1_kernel(const float* __restrict__ x, const float* __restrict__ W1) {
    mma_gemm_body<IN_C>(x, W1, g_bufA);
}
__global__ __launch_bounds__(256, 2)
void gemm2_kernel(const float* __restrict__ W2) {
    mma_gemm_body<HID>(g_bufB, W2, g_bufA);
}

// ---------------- aggregation: pull-mode, 1 warp per dst node --------------
__global__ void agg_kernel(const float* __restrict__ bias) {
    int w = (blockIdx.x * blockDim.x + threadIdx.x) >> 5;
    int lane = threadIdx.x & 31;
    if (w >= N_NODES) return;
    const float* __restrict__ h = g_bufA;
    float dv = g_dinv[w];
    float4 sv = *(const float4*)(h + (size_t)w * HID + lane * 4);
    float4 acc = make_float4(dv * sv.x, dv * sv.y, dv * sv.z, dv * sv.w);
    int beg = g_rowptr[w], end = g_rowptr[w + 1];
    for (int e = beg; e < end; e++) {
        int s = g_col[e];
        float ws = g_dinv[s];
        float4 v = *(const float4*)(h + (size_t)s * HID + lane * 4);
        acc.x += ws * v.x; acc.y += ws * v.y;
        acc.z += ws * v.z; acc.w += ws * v.w;
    }
    float4 b = *(const float4*)(bias + lane * 4);
    float4 o;
    o.x = fmaxf(dv * acc.x + b.x, 0.0f);
    o.y = fmaxf(dv * acc.y + b.y, 0.0f);
    o.z = fmaxf(dv * acc.z + b.z, 0.0f);
    o.w = fmaxf(dv * acc.w + b.w, 0.0f);
    *(float4*)(g_bufB + (size_t)w * HID + lane * 4) = o;
}

// ------- layer-2 aggregation with fused mean-pool --------------------------
__global__ void agg_pool_kernel(const float* __restrict__ bias,
                                const int* __restrict__ bids) {
    int w = (blockIdx.x * blockDim.x + threadIdx.x) >> 5;
    int lane = threadIdx.x & 31;
    if (w >= N_NODES) return;
    const float* __restrict__ h = g_bufA;
    float dv = g_dinv[w];
    float4 sv = *(const float4*)(h + (size_t)w * HID + lane * 4);
    float4 acc = make_float4(dv * sv.x, dv * sv.y, dv * sv.z, dv * sv.w);
    int beg = g_rowptr[w], end = g_rowptr[w + 1];
    for (int e = beg; e < end; e++) {
        int s = g_col[e];
        float ws = g_dinv[s];
        float4 v = *(const float4*)(h + (size_t)s * HID + lane * 4);
        acc.x += ws * v.x; acc.y += ws * v.y;
        acc.z += ws * v.z; acc.w += ws * v.w;
    }
    float4 b = *(const float4*)(bias + lane * 4);
    float4 o;
    o.x = fmaxf(dv * acc.x + b.x, 0.0f);
    o.y = fmaxf(dv * acc.y + b.y, 0.0f);
    o.z = fmaxf(dv * acc.z + b.z, 0.0f);
    o.w = fmaxf(dv * acc.w + b.w, 0.0f);
    unsigned gr = (unsigned)bids[w];
    if (gr >= N_GRAPHS) gr = 0;
    float* p = &g_pool[gr * HID + lane * 4];
    atomicAdd(p + 0, o.x);
    atomicAdd(p + 1, o.y);
    atomicAdd(p + 2, o.z);
    atomicAdd(p + 3, o.w);
    if (lane == 0) atomicAdd(&g_cntg[gr], 1.0f);
}

// ---------------- final linear head: 1 warp per graph ----------------------
__global__ void final_kernel(const float* __restrict__ Wlin,
                             const float* __restrict__ blin,
                             float* __restrict__ out) {
    int g = (blockIdx.x * blockDim.x + threadIdx.x) >> 5;
    int lane = threadIdx.x & 31;
    if (g >= N_GRAPHS) return;
    float inv = 1.0f / fmaxf(g_cntg[g], 1.0f);
    float4 p = *(const float4*)(&g_pool[g * HID + lane * 4]);
    p.x *= inv; p.y *= inv; p.z *= inv; p.w *= inv;
    int c = lane * 4;
    float s0 = p.x * Wlin[c * 2]       + p.y * Wlin[(c + 1) * 2]
             + p.z * Wlin[(c + 2) * 2] + p.w * Wlin[(c + 3) * 2];
    float s1 = p.x * Wlin[c * 2 + 1]       + p.y * Wlin[(c + 1) * 2 + 1]
             + p.z * Wlin[(c + 2) * 2 + 1] + p.w * Wlin[(c + 3) * 2 + 1];
    #pragma unroll
    for (int off = 16; off > 0; off >>= 1) {
        s0 += __shfl_xor_sync(0xFFFFFFFF, s0, off);
        s1 += __shfl_xor_sync(0xFFFFFFFF, s1, off);
    }
    if (lane == 0) {
        out[g * 2 + 0] = s0 + blin[0];
        out[g * 2 + 1] = s1 + blin[1];
    }
}

// ---------------- launch ----------------------------------------------------
extern "C" void kernel_launch(void* const* d_in, const int* in_sizes, int n_in,
                              void* d_out, int out_size) {
    const float* x    = (const float*)d_in[0];
    const int*   edge = (const int*)d_in[1];
    const int*   bids = (const int*)d_in[2];
    const float* W1   = (const float*)d_in[3];
    const float* b1   = (const float*)d_in[4];
    const float* W2   = (const float*)d_in[5];
    const float* b2   = (const float*)d_in[6];
    const float* Wlin = (const float*)d_in[7];
    const float* blin = (const float*)d_in[8];
    float*       out  = (float*)d_out;

    // side stream for CSR build (independent of GEMM1) — created once
    static cudaStream_t sCsr = nullptr;
    static cudaEvent_t evFork = nullptr, evJoin = nullptr;
    if (!sCsr) {
        cudaStreamCreateWithFlags(&sCsr, cudaStreamNonBlocking);
        cudaEventCreateWithFlags(&evFork, cudaEventDisableTiming);
        cudaEventCreateWithFlags(&evJoin, cudaEventDisableTiming);
    }

    int gemmGrid = N_NODES / 128;   // 788, exact
    int aggBlocks = (N_NODES * 32 + 255) / 256;
    int e4Blocks = (N_EDGES / 4 + 255) / 256;

    // fork: CSR build runs concurrently with GEMM1
    cudaEventRecord(evFork, 0);
    cudaStreamWaitEvent(sCsr, evFork, 0);
    init_kernel<<<(N_NODES + 255) / 256, 256, 0, sCsr>>>();
    count_kernel<<<e4Blocks, 256, 0, sCsr>>>(edge);
    scan_kernel<<<1, 1024, 0, sCsr>>>();
    fill_kernel<<<e4Blocks, 256, 0, sCsr>>>(edge);
    cudaEventRecord(evJoin, sCsr);

    gemm1_kernel<<<gemmGrid, 256>>>(x, W1);       // main stream
    cudaStreamWaitEvent(0, evJoin, 0);            // join before aggregation

    agg_kernel<<<aggBlocks, 256>>>(b1);
    gemm2_kernel<<<gemmGrid, 256>>>(W2);
    agg_pool_kernel<<<aggBlocks, 256>>>(b2, bids);
    final_kernel<<<(N_GRAPHS * 32 + 255) / 256, 256>>>(Wlin, blin, out);
}

// round 9
// speedup vs baseline: 1.0307x; 1.0307x over previous
#include <cuda_runtime.h>
#include <cuda_bf16.h>
#include <math.h>

#define N_NODES 100864
#define N_EDGES 1613824
#define N_GRAPHS 512
#define IN_C 384
#define HID 128
#define OUT_C 2

// ---------------- scratch (static __device__, no allocs) ----------------
__device__ int   g_cnt[N_NODES];
__device__ int   g_rowptr[N_NODES + 1];
__device__ int   g_fill[N_NODES];
__device__ int   g_col[N_EDGES];
__device__ __align__(16) float g_dinv[N_NODES];
__device__ __align__(16) float g_bufA[(size_t)N_NODES * HID];  // GEMM out (pre-scaled by dinv[row])
__device__ __align__(16) float g_bufB[(size_t)N_NODES * HID];  // agg out
__device__ __align__(16) float g_pool[N_GRAPHS * HID];
__device__ __align__(16) float g_cntg[N_GRAPHS];

// ---------------- init ----------------
__global__ void init_kernel() {
    int i = blockIdx.x * blockDim.x + threadIdx.x;
    if (i < N_NODES) g_cnt[i] = 0;
    if (i < N_GRAPHS * HID) g_pool[i] = 0.0f;
    if (i < N_GRAPHS) g_cntg[i] = 0.0f;
}

// ---------------- degree count (dst side) ----------------
__global__ void count_kernel(const int* __restrict__ edge) {
    int e = blockIdx.x * blockDim.x + threadIdx.x;
    if (e >= N_EDGES) return;
    unsigned dst = (unsigned)edge[N_EDGES + e];
    if (dst >= N_NODES) dst = 0;
    atomicAdd(&g_cnt[dst], 1);
}

// ---------------- single-block scan: rowptr, fill, dinv ----------------
__global__ void scan_kernel() {
    __shared__ int sh[1024];
    const int n = N_NODES;
    const int C = (n + 1023) / 1024;
    int t = threadIdx.x;
    int beg = t * C;
    int end = beg + C; if (end > n) end = n;
    int s = 0;
    for (int i = beg; i < end; i++) s += g_cnt[i];
    sh[t] = s;
    __syncthreads();
    for (int off = 1; off < 1024; off <<= 1) {
        int v = (t >= off) ? sh[t - off] : 0;
        __syncthreads();
        sh[t] += v;
        __syncthreads();
    }
    int run = (t == 0) ? 0 : sh[t - 1];
    for (int i = beg; i < end; i++) {
        int c = g_cnt[i];
        g_rowptr[i] = run;
        g_fill[i]   = run;
        g_dinv[i]   = rsqrtf((float)c + 1.0f);  // +1 self-loop
        run += c;
    }
    if (t == 1023) g_rowptr[n] = run;
}

// ---------------- CSR fill ----------------
__global__ void fill_kernel(const int* __restrict__ edge) {
    int e = blockIdx.x * blockDim.x + threadIdx.x;
    if (e >= N_EDGES) return;
    unsigned src = (unsigned)edge[e];
    unsigned dst = (unsigned)edge[N_EDGES + e];
    if (src >= N_NODES) src = 0;
    if (dst >= N_NODES) dst = 0;
    int p = atomicAdd(&g_fill[dst], 1);
    g_col[p] = (int)src;
}

// ---------------- tf32 helpers ----------------
__device__ __forceinline__ void split2(float x, unsigned& hi, unsigned& lo) {
    unsigned h; asm("cvt.rna.tf32.f32 %0, %1;" : "=r"(h) : "f"(x));
    float hf = __uint_as_float(h);
    unsigned l; asm("cvt.rna.tf32.f32 %0, %1;" : "=r"(l) : "f"(x - hf));
    hi = h; lo = l;
}
__device__ __forceinline__ void mma8(float* d, const unsigned* a, const unsigned* b) {
    asm("mma.sync.aligned.m16n8k8.row.col.f32.tf32.tf32.f32 "
        "{%0,%1,%2,%3},{%4,%5,%6,%7},{%8,%9},{%0,%1,%2,%3};"
        : "+f"(d[0]), "+f"(d[1]), "+f"(d[2]), "+f"(d[3])
        : "r"(a[0]), "r"(a[1]), "r"(a[2]), "r"(a[3]), "r"(b[0]), "r"(b[1]));
}

// ---- tensor-core GEMM (R6-proven): C[M,128] = dinv[row] * (A[M,K] @ B[K,128])
// block tile 128x128, BK=32, 8 warps (4 M x 2 N), warp tile 32x64 (2x8 m16n8k8)
template<int K>
__device__ __forceinline__ void mma_gemm_body(const float* __restrict__ A,
                                              const float* __restrict__ B,
                                              float* __restrict__ C) {
    __shared__ float As[32][136];   // [k][m]
    __shared__ float Bs[32][136];   // [k][n]
    const int tid  = threadIdx.x;
    const int lane = tid & 31;
    const int warp = tid >> 5;
    const int g    = lane >> 2, tig = lane & 3;
    const int warpM = warp >> 1, warpN = warp & 1;
    const int rowBase = blockIdx.x * 128;

    float acc[2][8][4];
    #pragma unroll
    for (int mt = 0; mt < 2; mt++)
        #pragma unroll
        for (int nt = 0; nt < 8; nt++)
            #pragma unroll
            for (int i = 0; i < 4; i++) acc[mt][nt][i] = 0.0f;

    const int aRow = tid >> 1, aK = (tid & 1) * 16;
    const int bK = tid >> 3,  bN = (tid & 7) * 16;

    for (int k0 = 0; k0 < K; k0 += 32) {
        #pragma unroll
        for (int i = 0; i < 4; i++) {
            float4 v = *(const float4*)&A[(size_t)(rowBase + aRow) * K + (k0 + aK + i * 4)];
            As[aK + i * 4 + 0][aRow] = v.x;
            As[aK + i * 4 + 1][aRow] = v.y;
            As[aK + i * 4 + 2][aRow] = v.z;
            As[aK + i * 4 + 3][aRow] = v.w;
        }
        #pragma unroll
        for (int i = 0; i < 4; i++) {
            *(float4*)&Bs[bK][bN + i * 4] =
                *(const float4*)&B[(size_t)(k0 + bK) * 128 + bN + i * 4];
        }
        __syncthreads();
        #pragma unroll
        for (int kk = 0; kk < 4; kk++) {
            const int kb = kk * 8;
            unsigned ah[2][4], al[2][4];
            #pragma unroll
            for (int mt = 0; mt < 2; mt++) {
                int r0 = warpM * 32 + mt * 16 + g;
                split2(As[kb + tig    ][r0    ], ah[mt][0], al[mt][0]);
                split2(As[kb + tig    ][r0 + 8], ah[mt][1], al[mt][1]);
                split2(As[kb + tig + 4][r0    ], ah[mt][2], al[mt][2]);
                split2(As[kb + tig + 4][r0 + 8], ah[mt][3], al[mt][3]);
            }
            #pragma unroll
            for (int nt = 0; nt < 8; nt++) {
                int c0 = warpN * 64 + nt * 8 + g;
                unsigned bh[2], bl[2];
                split2(Bs[kb + tig    ][c0], bh[0], bl[0]);
                split2(Bs[kb + tig + 4][c0], bh[1], bl[1]);
                #pragma unroll
                for (int mt = 0; mt < 2; mt++) {
                    mma8(acc[mt][nt], ah[mt], bh);
                    mma8(acc[mt][nt], al[mt], bh);
                    mma8(acc[mt][nt], ah[mt], bl);
                }
            }
        }
        __syncthreads();
    }
    // epilogue: scale row r by dinv[r] (pre-normalizes messages for the agg)
    #pragma unroll
    for (int mt = 0; mt < 2; mt++) {
        int r = rowBase + warpM * 32 + mt * 16 + g;
        float d0 = g_dinv[r], d1 = g_dinv[r + 8];
        #pragma unroll
        for (int nt = 0; nt < 8; nt++) {
            int c = warpN * 64 + nt * 8 + tig * 2;
            *(float2*)&C[(size_t)r * 128 + c] =
                make_float2(acc[mt][nt][0] * d0, acc[mt][nt][1] * d0);
            *(float2*)&C[(size_t)(r + 8) * 128 + c] =
                make_float2(acc[mt][nt][2] * d1, acc[mt][nt][3] * d1);
        }
    }
}

__global__ __launch_bounds__(256, 2)
void gemm1_kernel(const float* __restrict__ x, const float* __restrict__ W1) {
    mma_gemm_body<IN_C>(x, W1, g_bufA);
}
__global__ __launch_bounds__(256, 2)
void gemm2_kernel(const float* __restrict__ W2) {
    mma_gemm_body<HID>(g_bufB, W2, g_bufA);
}

// ------------- aggregation core: shuffle-broadcast idx, 4x-unrolled gather --
// h rows are pre-scaled by dinv[src]. out_v = dinv[v]*(sum_neigh + h[v]) + b
__device__ __forceinline__ float4 agg_node(int w, int lane, const float* __restrict__ h) {
    float4 sv = *(const float4*)(h + (size_t)w * HID + lane * 4);
    float4 acc = sv;                       // self term h'[v] = dinv[v]*h[v]
    int beg = g_rowptr[w], end = g_rowptr[w + 1];
    for (int c0 = beg; c0 < end; c0 += 32) {
        int n = end - c0; if (n > 32) n = 32;
        int myIdx = (lane < n) ? g_col[c0 + lane] : 0;
        int i = 0;
        for (; i + 4 <= n; i += 4) {
            int s0 = __shfl_sync(0xFFFFFFFF, myIdx, i);
            int s1 = __shfl_sync(0xFFFFFFFF, myIdx, i + 1);
            int s2 = __shfl_sync(0xFFFFFFFF, myIdx, i + 2);
            int s3 = __shfl_sync(0xFFFFFFFF, myIdx, i + 3);
            float4 v0 = *(const float4*)(h + (size_t)s0 * HID + lane * 4);
            float4 v1 = *(const float4*)(h + (size_t)s1 * HID + lane * 4);
            float4 v2 = *(const float4*)(h + (size_t)s2 * HID + lane * 4);
            float4 v3 = *(const float4*)(h + (size_t)s3 * HID + lane * 4);
            acc.x += (v0.x + v1.x) + (v2.x + v3.x);
            acc.y += (v0.y + v1.y) + (v2.y + v3.y);
            acc.z += (v0.z + v1.z) + (v2.z + v3.z);
            acc.w += (v0.w + v1.w) + (v2.w + v3.w);
        }
        for (; i < n; i++) {
            int s = __shfl_sync(0xFFFFFFFF, myIdx, i);
            float4 v = *(const float4*)(h + (size_t)s * HID + lane * 4);
            acc.x += v.x; acc.y += v.y; acc.z += v.z; acc.w += v.w;
        }
    }
    return acc;
}

// layer-1 agg -> bufB
__global__ void agg_kernel(const float* __restrict__ bias) {
    int w = (blockIdx.x * blockDim.x + threadIdx.x) >> 5;
    int lane = threadIdx.x & 31;
    if (w >= N_NODES) return;
    float4 acc = agg_node(w, lane, g_bufA);
    float dv = g_dinv[w];
    float4 b = *(const float4*)(bias + lane * 4);
    float4 o;
    o.x = fmaxf(dv * acc.x + b.x, 0.0f);
    o.y = fmaxf(dv * acc.y + b.y, 0.0f);
    o.z = fmaxf(dv * acc.z + b.z, 0.0f);
    o.w = fmaxf(dv * acc.w + b.w, 0.0f);
    *(float4*)(g_bufB + (size_t)w * HID + lane * 4) = o;
}

// layer-2 agg + fused mean-pool
__global__ void agg_pool_kernel(const float* __restrict__ bias,
                                const int* __restrict__ bids) {
    int w = (blockIdx.x * blockDim.x + threadIdx.x) >> 5;
    int lane = threadIdx.x & 31;
    if (w >= N_NODES) return;
    float4 acc = agg_node(w, lane, g_bufA);
    float dv = g_dinv[w];
    float4 b = *(const float4*)(bias + lane * 4);
    float4 o;
    o.x = fmaxf(dv * acc.x + b.x, 0.0f);
    o.y = fmaxf(dv * acc.y + b.y, 0.0f);
    o.z = fmaxf(dv * acc.z + b.z, 0.0f);
    o.w = fmaxf(dv * acc.w + b.w, 0.0f);
    unsigned gr = (unsigned)bids[w];
    if (gr >= N_GRAPHS) gr = 0;
    float* p = &g_pool[gr * HID + lane * 4];
    atomicAdd(p + 0, o.x);
    atomicAdd(p + 1, o.y);
    atomicAdd(p + 2, o.z);
    atomicAdd(p + 3, o.w);
    if (lane == 0) atomicAdd(&g_cntg[gr], 1.0f);
}

// ---------------- final linear head: 1 warp per graph ----------------------
__global__ void final_kernel(const float* __restrict__ Wlin,
                             const float* __restrict__ blin,
                             float* __restrict__ out) {
    int g = (blockIdx.x * blockDim.x + threadIdx.x) >> 5;
    int lane = threadIdx.x & 31;
    if (g >= N_GRAPHS) return;
    float inv = 1.0f / fmaxf(g_cntg[g], 1.0f);
    float4 p = *(const float4*)(&g_pool[g * HID + lane * 4]);
    p.x *= inv; p.y *= inv; p.z *= inv; p.w *= inv;
    int c = lane * 4;
    float s0 = p.x * Wlin[c * 2]       + p.y * Wlin[(c + 1) * 2]
             + p.z * Wlin[(c + 2) * 2] + p.w * Wlin[(c + 3) * 2];
    float s1 = p.x * Wlin[c * 2 + 1]       + p.y * Wlin[(c + 1) * 2 + 1]
             + p.z * Wlin[(c + 2) * 2 + 1] + p.w * Wlin[(c + 3) * 2 + 1];
    #pragma unroll
    for (int off = 16; off > 0; off >>= 1) {
        s0 += __shfl_xor_sync(0xFFFFFFFF, s0, off);
        s1 += __shfl_xor_sync(0xFFFFFFFF, s1, off);
    }
    if (lane == 0) {
        out[g * 2 + 0] = s0 + blin[0];
        out[g * 2 + 1] = s1 + blin[1];
    }
}

// ---------------- launch (single stream, R6 ordering) -----------------------
extern "C" void kernel_launch(void* const* d_in, const int* in_sizes, int n_in,
                              void* d_out, int out_size) {
    const float* x    = (const float*)d_in[0];
    const int*   edge = (const int*)d_in[1];
    const int*   bids = (const int*)d_in[2];
    const float* W1   = (const float*)d_in[3];
    const float* b1   = (const float*)d_in[4];
    const float* W2   = (const float*)d_in[5];
    const float* b2   = (const float*)d_in[6];
    const float* Wlin = (const float*)d_in[7];
    const float* blin = (const float*)d_in[8];
    float*       out  = (float*)d_out;

    init_kernel<<<(N_NODES + 255) / 256, 256>>>();
    count_kernel<<<(N_EDGES + 255) / 256, 256>>>(edge);
    scan_kernel<<<1, 1024>>>();
    fill_kernel<<<(N_EDGES + 255) / 256, 256>>>(edge);

    int gemmGrid = N_NODES / 128;   // 788, exact
    int aggBlocks = (N_NODES * 32 + 255) / 256;

    gemm1_kernel<<<gemmGrid, 256>>>(x, W1);
    agg_kernel<<<aggBlocks, 256>>>(b1);
    gemm2_kernel<<<gemmGrid, 256>>>(W2);
    agg_pool_kernel<<<aggBlocks, 256>>>(b2, bids);
    final_kernel<<<(N_GRAPHS * 32 + 255) / 256, 256>>>(Wlin, blin, out);
}